// round 1
// baseline (speedup 1.0000x reference)
#include <cuda_runtime.h>
#include <math.h>

#define BATCH 16384
#define ENC_LEN 48
#define ENC_HID 128
#define DEC_DIM 32
#define IN_DIM 4
#define T_DEC 12

__device__ __forceinline__ float warp_sum(float v) {
#pragma unroll
    for (int o = 16; o; o >>= 1) v += __shfl_xor_sync(0xffffffffu, v, o);
    return v;
}
__device__ __forceinline__ float warp_max(float v) {
#pragma unroll
    for (int o = 16; o; o >>= 1) v = fmaxf(v, __shfl_xor_sync(0xffffffffu, v, o));
    return v;
}

__global__ __launch_bounds__(128, 4)
void decoder_kernel(const float* __restrict__ y,
                    const float* __restrict__ enc,
                    const float* __restrict__ hidden,
                    const float* __restrict__ attn_W, const float* __restrict__ attn_b,
                    const float* __restrict__ comb_W, const float* __restrict__ comb_b,
                    const float* __restrict__ w_ih, const float* __restrict__ w_hh,
                    const float* __restrict__ b_ih, const float* __restrict__ b_hh,
                    const float* __restrict__ fc_W, const float* __restrict__ fc_b,
                    float* __restrict__ out)
{
    // transposed weights in smem: output-index is the fast (lane) dimension -> conflict-free
    __shared__ float aWT[36 * 48];            // aWT[j][e] = attn_W[e][j]
    __shared__ float attnb[48];
    __shared__ float whhT[32 * 96];           // whhT[j][g] = w_hh[g][j]
    __shared__ float wihT[4 * 96];            // wihT[k][g] = w_ih[g][k]
    __shared__ __align__(16) float cWT[132 * 4];  // cWT[d][i] = comb_W[i][d]
    __shared__ float cb[4];
    __shared__ float bih[96];
    __shared__ float bhh[96];
    __shared__ float fcw[32];
    __shared__ float fcb;
    // per-step state / scratch
    __shared__ float h_sm[32];
    __shared__ float xs[4];
    __shared__ float lg[48];
    __shared__ __align__(16) float aw[48];
    __shared__ float gh_sm[96];
    __shared__ float rz[64];
    __shared__ float gin[32];
    __shared__ float xpart[4][4];

    const int tid = threadIdx.x;
    const int wi = tid >> 5;
    const int lane = tid & 31;
    const int b = blockIdx.x;

    // ---- init: stage transposed weights ----
    for (int i = tid; i < 48 * 36; i += 128) {
        int e = i / 36, j = i % 36;
        aWT[j * 48 + e] = attn_W[i];
    }
    for (int i = tid; i < 96 * 32; i += 128) {
        int g = i / 32, j = i % 32;
        whhT[j * 96 + g] = w_hh[i];
    }
    for (int i = tid; i < 96 * 4; i += 128) {
        int g = i / 4, k = i % 4;
        wihT[k * 96 + g] = w_ih[i];
    }
    for (int i = tid; i < 4 * 132; i += 128) {
        int r = i / 132, d = i % 132;
        cWT[d * 4 + r] = comb_W[i];
    }
    if (tid < 48) attnb[tid] = attn_b[tid];
    if (tid < 96) { bih[tid] = b_ih[tid]; bhh[tid] = b_hh[tid]; }
    if (tid < 32) { fcw[tid] = fc_W[tid]; h_sm[tid] = hidden[b * DEC_DIM + tid]; }
    if (tid < 4) cb[tid] = comb_b[tid];
    if (tid == 0) fcb = fc_b[0];
    if (tid < 4) {
        // x0 = nan_to_num(y_[0])
        float v = y[b * 52 + tid];
        if (isnan(v)) v = 0.f;
        else if (isinf(v)) v = (v > 0.f) ? 3.4028234663852886e38f : -3.4028234663852886e38f;
        xs[tid] = v;
    }

    // enc column `tid` of this batch element, register-resident: read HBM exactly once
    float er[48];
#pragma unroll
    for (int e = 0; e < ENC_LEN; e++)
        er[e] = enc[(e * BATCH + b) * ENC_HID + tid];

    __syncthreads();

    for (int t = 0; t < T_DEC; t++) {
        // ---- Phase A: warps 0/1: attention logits; warps 2/3: gh = h @ w_hh^T + b_hh ----
        if (wi < 2) {
            int e = wi * 32 + lane;
            if (e < 48) {
                float acc = attnb[e];
#pragma unroll
                for (int j = 0; j < 4; j++) acc = fmaf(xs[j], aWT[j * 48 + e], acc);
#pragma unroll
                for (int j = 0; j < 32; j++) acc = fmaf(h_sm[j], aWT[(4 + j) * 48 + e], acc);
                lg[e] = acc;
            }
        } else {
            const int g1 = (wi == 2) ? lane : 32 + lane;
            const int g2 = (wi == 2) ? 64 + lane : 80 + lane;
            const bool has2 = lane < 16;
            float a1 = bhh[g1];
            float a2 = has2 ? bhh[g2] : 0.f;
#pragma unroll
            for (int j = 0; j < 32; j++) {
                float hj = h_sm[j];
                a1 = fmaf(hj, whhT[j * 96 + g1], a1);
                if (has2) a2 = fmaf(hj, whhT[j * 96 + g2], a2);
            }
            gh_sm[g1] = a1;
            if (has2) gh_sm[g2] = a2;
        }
        __syncthreads();

        // ---- Phase B: softmax over 48 logits (warp 0) ----
        if (wi == 0) {
            float v0 = lg[lane];
            float v1 = (lane < 16) ? lg[32 + lane] : -3.4e38f;
            float m = warp_max(fmaxf(v0, v1));
            float e0 = expf(v0 - m);
            float e1 = (lane < 16) ? expf(v1 - m) : 0.f;
            float s = warp_sum(e0 + e1);
            float inv = 1.f / s;
            aw[lane] = e0 * inv;
            if (lane < 16) aw[32 + lane] = e1 * inv;
        }
        __syncthreads();

        // ---- Phase C: ctx (pure register FMA) + x2 partial reduction ----
        {
            float c0 = 0.f, c1 = 0.f, c2 = 0.f, c3 = 0.f;
#pragma unroll
            for (int e = 0; e < 48; e += 4) {
                float4 a4 = *(const float4*)&aw[e];
                c0 = fmaf(a4.x, er[e + 0], c0);
                c1 = fmaf(a4.y, er[e + 1], c1);
                c2 = fmaf(a4.z, er[e + 2], c2);
                c3 = fmaf(a4.w, er[e + 3], c3);
            }
            float ctx = (c0 + c1) + (c2 + c3);
            float4 cw = *(const float4*)&cWT[tid * 4];
            float p0 = ctx * cw.x, p1 = ctx * cw.y, p2 = ctx * cw.z, p3 = ctx * cw.w;
            p0 = warp_sum(p0); p1 = warp_sum(p1); p2 = warp_sum(p2); p3 = warp_sum(p3);
            if (lane == 0) {
                xpart[wi][0] = p0; xpart[wi][1] = p1;
                xpart[wi][2] = p2; xpart[wi][3] = p3;
            }
        }
        __syncthreads();

        // ---- Phase D: finalize x2, gi, sigmoid for r/z ----
        if (tid < 96) {
            float x2[4];
#pragma unroll
            for (int i = 0; i < 4; i++) {
                float v = cb[i] + xpart[0][i] + xpart[1][i] + xpart[2][i] + xpart[3][i];
#pragma unroll
                for (int k = 0; k < 4; k++) v = fmaf(xs[k], cWT[(128 + k) * 4 + i], v);
                x2[i] = v;
            }
            const int g = tid;
            float gi = bih[g];
#pragma unroll
            for (int k = 0; k < 4; k++) gi = fmaf(x2[k], wihT[k * 96 + g], gi);
            if (g < 64) {
                float a = gi + gh_sm[g];
                rz[g] = 1.f / (1.f + expf(-a));
            } else {
                gin[g - 64] = gi;   // i_n (gh_n kept separate in gh_sm)
            }
        }
        __syncthreads();

        // ---- Phase E: h update, fc output, next x ----
        if (wi == 0) {
            float r = rz[lane];
            float z = rz[32 + lane];
            float n = tanhf(gin[lane] + r * gh_sm[64 + lane]);
            float hn = (1.f - z) * n + z * h_sm[lane];
            h_sm[lane] = hn;
            float p = warp_sum(hn * fcw[lane]);
            if (lane == 0) {
                float o = p + fcb;
                out[t * BATCH + b] = o;
                xs[3] = o;
            }
        } else if (wi == 1 && lane < 3) {
            xs[lane] = y[b * 52 + (t + 1) * 4 + (lane + 1)];
        }
        __syncthreads();
    }
}

extern "C" void kernel_launch(void* const* d_in, const int* in_sizes, int n_in,
                              void* d_out, int out_size) {
    const float* y      = (const float*)d_in[0];
    const float* enc    = (const float*)d_in[1];
    const float* hidden = (const float*)d_in[2];
    // d_in[3] = batch_ids (unused by reference)
    const float* attn_W = (const float*)d_in[4];
    const float* attn_b = (const float*)d_in[5];
    const float* comb_W = (const float*)d_in[6];
    const float* comb_b = (const float*)d_in[7];
    const float* w_ih   = (const float*)d_in[8];
    const float* w_hh   = (const float*)d_in[9];
    const float* b_ih   = (const float*)d_in[10];
    const float* b_hh   = (const float*)d_in[11];
    const float* fc_W   = (const float*)d_in[12];
    const float* fc_b   = (const float*)d_in[13];

    decoder_kernel<<<BATCH, 128>>>(y, enc, hidden, attn_W, attn_b, comb_W, comb_b,
                                   w_ih, w_hh, b_ih, b_hh, fc_W, fc_b, (float*)d_out);
}

// round 2
// speedup vs baseline: 1.8334x; 1.8334x over previous
#include <cuda_runtime.h>
#include <math.h>

#define B 16384
#define TDEC 12

// P[e][b][i] = dot(comb_W[i][0:128], enc[e][b][:])  — 12.6 MB scratch (L2-resident)
__device__ __align__(16) float g_P[48 * B * 4];

__constant__ float cAWx[48 * 4];    // attn_W[e][0..3]   (x part)
__constant__ float cAWh[48 * 32];   // attn_W[e][4..35]  (h part)
__constant__ float cAb[48];
__constant__ float cWhh[96 * 32];
__constant__ float cWih[96 * 4];
__constant__ float cBih[96];
__constant__ float cBhh[96];
__constant__ float cCWx[16];        // comb_W[i][128..131] (x tail)
__constant__ float cCb[4];
__constant__ float cFcW[32];
__constant__ float cFcb[1];

// ---------------- precompute kernel: P = enc @ comb_W128^T ----------------
// warp handles (e, 4 consecutive b); lanes split the 128-d dim (4 each, float4)
__global__ __launch_bounds__(256) void precompute_P(const float* __restrict__ enc,
                                                    const float* __restrict__ comb_W)
{
    __shared__ __align__(16) float sW[528];
    for (int i = threadIdx.x; i < 528; i += 256) sW[i] = comb_W[i];
    __syncthreads();

    const int lane = threadIdx.x & 31;
    const int gw = (blockIdx.x * 256 + threadIdx.x) >> 5;   // 0..196607
    const int e = gw >> 12;                                  // /4096
    const int b0 = (gw & 4095) << 2;

    const float4 w0 = *(const float4*)&sW[0 * 132 + lane * 4];
    const float4 w1 = *(const float4*)&sW[1 * 132 + lane * 4];
    const float4 w2 = *(const float4*)&sW[2 * 132 + lane * 4];
    const float4 w3 = *(const float4*)&sW[3 * 132 + lane * 4];

    const float4* encp = (const float4*)(enc + ((size_t)e * B + b0) * 128);
#pragma unroll
    for (int bb = 0; bb < 4; bb++) {
        float4 v = encp[bb * 32 + lane];
        float p0 = v.x * w0.x; p0 = fmaf(v.y, w0.y, p0); p0 = fmaf(v.z, w0.z, p0); p0 = fmaf(v.w, w0.w, p0);
        float p1 = v.x * w1.x; p1 = fmaf(v.y, w1.y, p1); p1 = fmaf(v.z, w1.z, p1); p1 = fmaf(v.w, w1.w, p1);
        float p2 = v.x * w2.x; p2 = fmaf(v.y, w2.y, p2); p2 = fmaf(v.z, w2.z, p2); p2 = fmaf(v.w, w2.w, p2);
        float p3 = v.x * w3.x; p3 = fmaf(v.y, w3.y, p3); p3 = fmaf(v.z, w3.z, p3); p3 = fmaf(v.w, w3.w, p3);
#pragma unroll
        for (int o = 16; o; o >>= 1) {
            p0 += __shfl_xor_sync(0xffffffffu, p0, o);
            p1 += __shfl_xor_sync(0xffffffffu, p1, o);
            p2 += __shfl_xor_sync(0xffffffffu, p2, o);
            p3 += __shfl_xor_sync(0xffffffffu, p3, o);
        }
        if (lane == 0)
            ((float4*)g_P)[e * B + b0 + bb] = make_float4(p0, p1, p2, p3);
    }
}

// ---------------- decoder: element-per-lane, weights from constant ----------------
__device__ __forceinline__ float nfix(float v) {
    if (isnan(v)) return 0.f;
    return fminf(fmaxf(v, -3.4028234663852886e38f), 3.4028234663852886e38f);
}
__device__ __forceinline__ float fsigmoid(float s) {
    s = fminf(fmaxf(s, -30.f), 30.f);
    return __fdividef(1.f, 1.f + __expf(-s));
}
__device__ __forceinline__ float ftanh(float a) {
    a = fminf(fmaxf(a, -15.f), 15.f);
    float t = __expf(2.f * a);
    return 1.f - __fdividef(2.f, t + 1.f);
}

__global__ __launch_bounds__(32) void decoder_kernel(const float* __restrict__ y,
                                                     const float* __restrict__ hidden,
                                                     float* __restrict__ out)
{
    __shared__ float lg_sm[48][32];       // lane-private columns
    __shared__ float hn_sm[32][33];       // padded: also used for coalesced h staging
    const int lane = threadIdx.x;
    const int b0 = blockIdx.x * 32;
    const int b = b0 + lane;

    // coalesced load of hidden -> transposed into hn_sm[j][elem]
#pragma unroll
    for (int k = 0; k < 32; k++) {
        float v = hidden[b0 * 32 + k * 32 + lane];   // element k, component lane
        hn_sm[lane][k] = v;
    }
    __syncwarp();
    float h[32];
#pragma unroll
    for (int j = 0; j < 32; j++) h[j] = hn_sm[j][lane];

    float4 yv = *(const float4*)(y + (size_t)b * 52);
    float xA = nfix(yv.x), xB = nfix(yv.y), xC = nfix(yv.z), xD = nfix(yv.w);

    for (int t = 0; t < TDEC; t++) {
        // ---- attention logits (weights via constant port), running max ----
        float m = -3.4e38f;
#pragma unroll 4
        for (int e = 0; e < 48; e++) {
            float4 wx = *(const float4*)&cAWx[e * 4];
            float acc = cAb[e];
            acc = fmaf(xA, wx.x, acc); acc = fmaf(xB, wx.y, acc);
            acc = fmaf(xC, wx.z, acc); acc = fmaf(xD, wx.w, acc);
            const float4* wh4 = (const float4*)&cAWh[e * 32];
#pragma unroll
            for (int q = 0; q < 8; q++) {
                float4 w = wh4[q];
                acc = fmaf(h[4 * q + 0], w.x, acc);
                acc = fmaf(h[4 * q + 1], w.y, acc);
                acc = fmaf(h[4 * q + 2], w.z, acc);
                acc = fmaf(h[4 * q + 3], w.w, acc);
            }
            lg_sm[e][lane] = acc;
            m = fmaxf(m, acc);
        }
        // ---- softmax (in-lane, unnormalized; fold 1/s into ctx) ----
        float s = 0.f;
#pragma unroll 8
        for (int e = 0; e < 48; e++) {
            float v = __expf(lg_sm[e][lane] - m);
            lg_sm[e][lane] = v;
            s += v;
        }
        float inv = __fdividef(1.f, s);

        // ---- ctx projection via P (coalesced LDG.128, L2-resident) ----
        float c0 = 0.f, c1 = 0.f, c2 = 0.f, c3 = 0.f;
#pragma unroll 6
        for (int e = 0; e < 48; e++) {
            float a = lg_sm[e][lane];
            float4 p = __ldg(&((const float4*)g_P)[e * B + b]);
            c0 = fmaf(a, p.x, c0); c1 = fmaf(a, p.y, c1);
            c2 = fmaf(a, p.z, c2); c3 = fmaf(a, p.w, c3);
        }
        float4 cw0 = *(const float4*)&cCWx[0];
        float4 cw1 = *(const float4*)&cCWx[4];
        float4 cw2 = *(const float4*)&cCWx[8];
        float4 cw3 = *(const float4*)&cCWx[12];
        float X0 = fmaf(c0, inv, cCb[0]);
        X0 = fmaf(xA, cw0.x, X0); X0 = fmaf(xB, cw0.y, X0); X0 = fmaf(xC, cw0.z, X0); X0 = fmaf(xD, cw0.w, X0);
        float X1 = fmaf(c1, inv, cCb[1]);
        X1 = fmaf(xA, cw1.x, X1); X1 = fmaf(xB, cw1.y, X1); X1 = fmaf(xC, cw1.z, X1); X1 = fmaf(xD, cw1.w, X1);
        float X2 = fmaf(c2, inv, cCb[2]);
        X2 = fmaf(xA, cw2.x, X2); X2 = fmaf(xB, cw2.y, X2); X2 = fmaf(xC, cw2.z, X2); X2 = fmaf(xD, cw2.w, X2);
        float X3 = fmaf(c3, inv, cCb[3]);
        X3 = fmaf(xA, cw3.x, X3); X3 = fmaf(xB, cw3.y, X3); X3 = fmaf(xC, cw3.z, X3); X3 = fmaf(xD, cw3.w, X3);

        // ---- GRU cell (dynamic g loop; old h[g] read from smem copy) ----
#pragma unroll 2
        for (int g = 0; g < 32; g++) {
            float hg = hn_sm[g][lane];   // old h[g] (smem copy from previous step)

            float4 wir = *(const float4*)&cWih[g * 4];
            float sr = cBih[g] + cBhh[g];
            sr = fmaf(X0, wir.x, sr); sr = fmaf(X1, wir.y, sr);
            sr = fmaf(X2, wir.z, sr); sr = fmaf(X3, wir.w, sr);
            const float4* whr = (const float4*)&cWhh[g * 32];
#pragma unroll
            for (int q = 0; q < 8; q++) {
                float4 w = whr[q];
                sr = fmaf(h[4 * q + 0], w.x, sr); sr = fmaf(h[4 * q + 1], w.y, sr);
                sr = fmaf(h[4 * q + 2], w.z, sr); sr = fmaf(h[4 * q + 3], w.w, sr);
            }

            float4 wiz = *(const float4*)&cWih[(32 + g) * 4];
            float sz = cBih[32 + g] + cBhh[32 + g];
            sz = fmaf(X0, wiz.x, sz); sz = fmaf(X1, wiz.y, sz);
            sz = fmaf(X2, wiz.z, sz); sz = fmaf(X3, wiz.w, sz);
            const float4* whz = (const float4*)&cWhh[(32 + g) * 32];
#pragma unroll
            for (int q = 0; q < 8; q++) {
                float4 w = whz[q];
                sz = fmaf(h[4 * q + 0], w.x, sz); sz = fmaf(h[4 * q + 1], w.y, sz);
                sz = fmaf(h[4 * q + 2], w.z, sz); sz = fmaf(h[4 * q + 3], w.w, sz);
            }

            float4 win = *(const float4*)&cWih[(64 + g) * 4];
            float gin = cBih[64 + g];
            gin = fmaf(X0, win.x, gin); gin = fmaf(X1, win.y, gin);
            gin = fmaf(X2, win.z, gin); gin = fmaf(X3, win.w, gin);
            const float4* whn = (const float4*)&cWhh[(64 + g) * 32];
            float ghn = cBhh[64 + g];
#pragma unroll
            for (int q = 0; q < 8; q++) {
                float4 w = whn[q];
                ghn = fmaf(h[4 * q + 0], w.x, ghn); ghn = fmaf(h[4 * q + 1], w.y, ghn);
                ghn = fmaf(h[4 * q + 2], w.z, ghn); ghn = fmaf(h[4 * q + 3], w.w, ghn);
            }

            float r = fsigmoid(sr);
            float z = fsigmoid(sz);
            float n = ftanh(fmaf(r, ghn, gin));
            float hnew = fmaf(z, hg - n, n);   // (1-z)*n + z*h
            hn_sm[g][lane] = hnew;
        }

        // ---- commit h, fc output, next x ----
        float o = cFcb[0];
#pragma unroll
        for (int j = 0; j < 32; j++) {
            h[j] = hn_sm[j][lane];
            o = fmaf(h[j], cFcW[j], o);
        }
        out[t * B + b] = o;
        if (t < TDEC - 1) {
            float4 yn = *(const float4*)(y + (size_t)b * 52 + (t + 1) * 4);
            xA = yn.y; xB = yn.z; xC = yn.w; xD = o;
        }
    }
}

extern "C" void kernel_launch(void* const* d_in, const int* in_sizes, int n_in,
                              void* d_out, int out_size) {
    const float* y      = (const float*)d_in[0];
    const float* enc    = (const float*)d_in[1];
    const float* hidden = (const float*)d_in[2];
    // d_in[3] = batch_ids (unused)
    const char* attn_W  = (const char*)d_in[4];
    const float* attn_b = (const float*)d_in[5];
    const char* comb_W  = (const char*)d_in[6];
    const float* comb_b = (const float*)d_in[7];
    const float* w_ih   = (const float*)d_in[8];
    const float* w_hh   = (const float*)d_in[9];
    const float* b_ih   = (const float*)d_in[10];
    const float* b_hh   = (const float*)d_in[11];
    const float* fc_W   = (const float*)d_in[12];
    const float* fc_b   = (const float*)d_in[13];

    void *pAWx, *pAWh, *pAb, *pWhh, *pWih, *pBih, *pBhh, *pCWx, *pCb, *pFcW, *pFcb;
    cudaGetSymbolAddress(&pAWx, cAWx);
    cudaGetSymbolAddress(&pAWh, cAWh);
    cudaGetSymbolAddress(&pAb,  cAb);
    cudaGetSymbolAddress(&pWhh, cWhh);
    cudaGetSymbolAddress(&pWih, cWih);
    cudaGetSymbolAddress(&pBih, cBih);
    cudaGetSymbolAddress(&pBhh, cBhh);
    cudaGetSymbolAddress(&pCWx, cCWx);
    cudaGetSymbolAddress(&pCb,  cCb);
    cudaGetSymbolAddress(&pFcW, cFcW);
    cudaGetSymbolAddress(&pFcb, cFcb);

    // attn_W [48][36] -> x part [48][4] and h part [48][32]
    cudaMemcpy2DAsync(pAWx, 16, attn_W, 144, 16, 48, cudaMemcpyDeviceToDevice, 0);
    cudaMemcpy2DAsync(pAWh, 128, attn_W + 16, 144, 128, 48, cudaMemcpyDeviceToDevice, 0);
    // comb_W [4][132] -> x tail [4][4]
    cudaMemcpy2DAsync(pCWx, 16, comb_W + 512, 528, 16, 4, cudaMemcpyDeviceToDevice, 0);
    cudaMemcpyAsync(pAb,  attn_b, 48 * 4,  cudaMemcpyDeviceToDevice, 0);
    cudaMemcpyAsync(pWhh, w_hh, 96 * 32 * 4, cudaMemcpyDeviceToDevice, 0);
    cudaMemcpyAsync(pWih, w_ih, 96 * 4 * 4,  cudaMemcpyDeviceToDevice, 0);
    cudaMemcpyAsync(pBih, b_ih, 96 * 4, cudaMemcpyDeviceToDevice, 0);
    cudaMemcpyAsync(pBhh, b_hh, 96 * 4, cudaMemcpyDeviceToDevice, 0);
    cudaMemcpyAsync(pCb,  comb_b, 4 * 4, cudaMemcpyDeviceToDevice, 0);
    cudaMemcpyAsync(pFcW, fc_W, 32 * 4, cudaMemcpyDeviceToDevice, 0);
    cudaMemcpyAsync(pFcb, fc_b, 4, cudaMemcpyDeviceToDevice, 0);

    precompute_P<<<24576, 256>>>((const float*)d_in[1], (const float*)d_in[6]);
    decoder_kernel<<<512, 32>>>(y, hidden, (float*)d_out);
}

// round 3
// speedup vs baseline: 2.1270x; 1.1602x over previous
#include <cuda_runtime.h>
#include <math.h>

#define B 16384
#define TDEC 12

__constant__ float cAWx[48 * 4];    // attn_W[e][0..3]
__constant__ float cAWh[48 * 32];   // attn_W[e][4..35]
__constant__ float cAb[48];
__constant__ float cWih[96 * 4];
__constant__ float cBih[96];
__constant__ float cBhh[96];
__constant__ float cCWx[16];        // comb_W[i][128..131]
__constant__ float cCb[4];
__constant__ float cFcW[32];
__constant__ float cFcb[1];

__device__ __forceinline__ float nfix(float v) {
    if (isnan(v)) return 0.f;
    return fminf(fmaxf(v, -3.4028234663852886e38f), 3.4028234663852886e38f);
}
__device__ __forceinline__ float fsigmoid(float s) {
    s = fminf(fmaxf(s, -30.f), 30.f);
    return __fdividef(1.f, 1.f + __expf(-s));
}
__device__ __forceinline__ float ftanh(float a) {
    a = fminf(fmaxf(a, -15.f), 15.f);
    float t = __expf(2.f * a);
    return 1.f - __fdividef(2.f, t + 1.f);
}

__global__ __launch_bounds__(128, 4)
void fused_decoder(const float* __restrict__ y,
                   const float* __restrict__ enc,
                   const float* __restrict__ hidden,
                   const float* __restrict__ comb_W,
                   const float* __restrict__ w_hh,
                   float* __restrict__ out)
{
    __shared__ __align__(16) float4 P_sm[48][32];   // 24576 B: P[e][elem] (4 outs)
    __shared__ float whh_s[96 * 32];                // 12288 B
    __shared__ float h_sm[32][33];                  // 4224 B  (h[comp][elem], padded)
    __shared__ __align__(16) float4 cpart[4][32];   // 2048 B
    __shared__ float pmax[4][32];
    __shared__ float psum[4][32];
    __shared__ float opart[4][32];

    const int tid = threadIdx.x;
    const int w = tid >> 5;
    const int lane = tid & 31;
    const int b0 = blockIdx.x * 32;
    const int b = b0 + lane;

    // stage w_hh into smem (coalesced)
    for (int i = tid; i < 96 * 32; i += 128) whh_s[i] = w_hh[i];

    // stage hidden transposed: h_sm[j][elem]
    for (int i = tid; i < 32 * 32; i += 128) {
        int eb = i >> 5, j = i & 31;                // hidden[(b0+eb)*32 + j]
        h_sm[j][eb] = hidden[(size_t)(b0 + eb) * 32 + j];
    }

    // ---- pre-phase: P_sm[e][bl].i = dot(comb_W[i][0:128], enc[e][b0+bl][:]) ----
    {
        const int hb  = lane >> 4;       // which element of the pair
        const int l16 = lane & 15;       // dim slice: dims [8*l16, 8*l16+8)
        float wr[4][8];
#pragma unroll
        for (int i = 0; i < 4; i++)
#pragma unroll
            for (int k = 0; k < 8; k++)
                wr[i][k] = comb_W[i * 132 + l16 * 8 + k];

        for (int e = 0; e < 48; e++) {
#pragma unroll
            for (int u = 0; u < 4; u++) {
                const int bl = w * 8 + u * 2 + hb;
                const float4* row = (const float4*)(enc + ((size_t)e * B + b0 + bl) * 128);
                float4 v0 = row[l16 * 2 + 0];
                float4 v1 = row[l16 * 2 + 1];
                float va[8] = {v0.x, v0.y, v0.z, v0.w, v1.x, v1.y, v1.z, v1.w};
                float p[4];
#pragma unroll
                for (int i = 0; i < 4; i++) {
                    float a = va[0] * wr[i][0];
#pragma unroll
                    for (int k = 1; k < 8; k++) a = fmaf(va[k], wr[i][k], a);
                    p[i] = a;
                }
#pragma unroll
                for (int o = 8; o; o >>= 1) {
                    p[0] += __shfl_xor_sync(0xffffffffu, p[0], o);
                    p[1] += __shfl_xor_sync(0xffffffffu, p[1], o);
                    p[2] += __shfl_xor_sync(0xffffffffu, p[2], o);
                    p[3] += __shfl_xor_sync(0xffffffffu, p[3], o);
                }
                if (l16 == 0) P_sm[e][bl] = make_float4(p[0], p[1], p[2], p[3]);
            }
        }
    }
    __syncthreads();

    // per-warp full register copy of this lane-element's h and x
    float h[32];
#pragma unroll
    for (int j = 0; j < 32; j++) h[j] = h_sm[j][lane];

    float4 yv = *(const float4*)(y + (size_t)b * 52);
    float xA = nfix(yv.x), xB = nfix(yv.y), xC = nfix(yv.z), xD = nfix(yv.w);

    for (int t = 0; t < TDEC; t++) {
        // ---- phase 1: warp w computes logits e in [12w, 12w+12) ----
        float le[12];
        float mx = -3.4e38f;
#pragma unroll
        for (int j = 0; j < 12; j++) {
            const int e = 12 * w + j;
            float4 wx = *(const float4*)&cAWx[e * 4];
            float acc = cAb[e];
            acc = fmaf(xA, wx.x, acc); acc = fmaf(xB, wx.y, acc);
            acc = fmaf(xC, wx.z, acc); acc = fmaf(xD, wx.w, acc);
            const float4* wh4 = (const float4*)&cAWh[e * 32];
#pragma unroll
            for (int q = 0; q < 8; q++) {
                float4 wv = wh4[q];
                acc = fmaf(h[4 * q + 0], wv.x, acc);
                acc = fmaf(h[4 * q + 1], wv.y, acc);
                acc = fmaf(h[4 * q + 2], wv.z, acc);
                acc = fmaf(h[4 * q + 3], wv.w, acc);
            }
            le[j] = acc;
            mx = fmaxf(mx, acc);
        }
        pmax[w][lane] = mx;
        __syncthreads();   // B1

        // ---- phase 2: exp + partial ctx over own e-range ----
        float m = fmaxf(fmaxf(pmax[0][lane], pmax[1][lane]),
                        fmaxf(pmax[2][lane], pmax[3][lane]));
        float s = 0.f, c0 = 0.f, c1 = 0.f, c2 = 0.f, c3 = 0.f;
#pragma unroll
        for (int j = 0; j < 12; j++) {
            float ev = __expf(le[j] - m);
            s += ev;
            float4 p = P_sm[12 * w + j][lane];
            c0 = fmaf(ev, p.x, c0); c1 = fmaf(ev, p.y, c1);
            c2 = fmaf(ev, p.z, c2); c3 = fmaf(ev, p.w, c3);
        }
        psum[w][lane] = s;
        cpart[w][lane] = make_float4(c0, c1, c2, c3);
        __syncthreads();   // B2

        // ---- phase 3: X (redundant per warp) + GRU rows g in [8w, 8w+8) ----
        float S = psum[0][lane] + psum[1][lane] + psum[2][lane] + psum[3][lane];
        float inv = __fdividef(1.f, S);
        float4 q0 = cpart[0][lane], q1 = cpart[1][lane],
               q2 = cpart[2][lane], q3 = cpart[3][lane];
        float cs0 = (q0.x + q1.x) + (q2.x + q3.x);
        float cs1 = (q0.y + q1.y) + (q2.y + q3.y);
        float cs2 = (q0.z + q1.z) + (q2.z + q3.z);
        float cs3 = (q0.w + q1.w) + (q2.w + q3.w);
        float4 cw0 = *(const float4*)&cCWx[0];
        float4 cw1 = *(const float4*)&cCWx[4];
        float4 cw2 = *(const float4*)&cCWx[8];
        float4 cw3 = *(const float4*)&cCWx[12];
        float X0 = fmaf(cs0, inv, cCb[0]);
        X0 = fmaf(xA, cw0.x, X0); X0 = fmaf(xB, cw0.y, X0); X0 = fmaf(xC, cw0.z, X0); X0 = fmaf(xD, cw0.w, X0);
        float X1 = fmaf(cs1, inv, cCb[1]);
        X1 = fmaf(xA, cw1.x, X1); X1 = fmaf(xB, cw1.y, X1); X1 = fmaf(xC, cw1.z, X1); X1 = fmaf(xD, cw1.w, X1);
        float X2 = fmaf(cs2, inv, cCb[2]);
        X2 = fmaf(xA, cw2.x, X2); X2 = fmaf(xB, cw2.y, X2); X2 = fmaf(xC, cw2.z, X2); X2 = fmaf(xD, cw2.w, X2);
        float X3 = fmaf(cs3, inv, cCb[3]);
        X3 = fmaf(xA, cw3.x, X3); X3 = fmaf(xB, cw3.y, X3); X3 = fmaf(xC, cw3.z, X3); X3 = fmaf(xD, cw3.w, X3);

        float po = 0.f;
#pragma unroll 2
        for (int k = 0; k < 8; k++) {
            const int g = 8 * w + k;
            float hg = h[0];   // placeholder; replaced below via smem read
            hg = h_sm[g][lane];           // old h[g] (not yet overwritten this step)

            float4 wir = *(const float4*)&cWih[g * 4];
            float sr = cBih[g] + cBhh[g];
            sr = fmaf(X0, wir.x, sr); sr = fmaf(X1, wir.y, sr);
            sr = fmaf(X2, wir.z, sr); sr = fmaf(X3, wir.w, sr);
            const float4* whr = (const float4*)&whh_s[g * 32];
#pragma unroll
            for (int q = 0; q < 8; q++) {
                float4 wv = whr[q];
                sr = fmaf(h[4 * q + 0], wv.x, sr); sr = fmaf(h[4 * q + 1], wv.y, sr);
                sr = fmaf(h[4 * q + 2], wv.z, sr); sr = fmaf(h[4 * q + 3], wv.w, sr);
            }

            float4 wiz = *(const float4*)&cWih[(32 + g) * 4];
            float sz = cBih[32 + g] + cBhh[32 + g];
            sz = fmaf(X0, wiz.x, sz); sz = fmaf(X1, wiz.y, sz);
            sz = fmaf(X2, wiz.z, sz); sz = fmaf(X3, wiz.w, sz);
            const float4* whz = (const float4*)&whh_s[(32 + g) * 32];
#pragma unroll
            for (int q = 0; q < 8; q++) {
                float4 wv = whz[q];
                sz = fmaf(h[4 * q + 0], wv.x, sz); sz = fmaf(h[4 * q + 1], wv.y, sz);
                sz = fmaf(h[4 * q + 2], wv.z, sz); sz = fmaf(h[4 * q + 3], wv.w, sz);
            }

            float4 win = *(const float4*)&cWih[(64 + g) * 4];
            float gin = cBih[64 + g];
            gin = fmaf(X0, win.x, gin); gin = fmaf(X1, win.y, gin);
            gin = fmaf(X2, win.z, gin); gin = fmaf(X3, win.w, gin);
            const float4* whn = (const float4*)&whh_s[(64 + g) * 32];
            float ghn = cBhh[64 + g];
#pragma unroll
            for (int q = 0; q < 8; q++) {
                float4 wv = whn[q];
                ghn = fmaf(h[4 * q + 0], wv.x, ghn); ghn = fmaf(h[4 * q + 1], wv.y, ghn);
                ghn = fmaf(h[4 * q + 2], wv.z, ghn); ghn = fmaf(h[4 * q + 3], wv.w, ghn);
            }

            float r = fsigmoid(sr);
            float z = fsigmoid(sz);
            float n = ftanh(fmaf(r, ghn, gin));
            float hnew = fmaf(z, hg - n, n);
            h_sm[g][lane] = hnew;
            po = fmaf(hnew, cFcW[g], po);
        }
        opart[w][lane] = po;
        __syncthreads();   // B3

        // ---- phase 4: reload h, finish fc, advance x ----
        float o = cFcb[0] + ((opart[0][lane] + opart[1][lane]) +
                             (opart[2][lane] + opart[3][lane]));
#pragma unroll
        for (int j = 0; j < 32; j++) h[j] = h_sm[j][lane];
        if (w == 0) out[(size_t)t * B + b] = o;
        if (t < TDEC - 1) {
            float4 yn = *(const float4*)(y + (size_t)b * 52 + (t + 1) * 4);
            xA = yn.y; xB = yn.z; xC = yn.w; xD = o;
        }
    }
}

extern "C" void kernel_launch(void* const* d_in, const int* in_sizes, int n_in,
                              void* d_out, int out_size) {
    const float* y      = (const float*)d_in[0];
    const float* enc    = (const float*)d_in[1];
    const float* hidden = (const float*)d_in[2];
    // d_in[3] = batch_ids (unused)
    const char*  attn_W = (const char*)d_in[4];
    const float* attn_b = (const float*)d_in[5];
    const float* comb_W = (const float*)d_in[6];
    const float* comb_b = (const float*)d_in[7];
    const float* w_ih   = (const float*)d_in[8];
    const float* w_hh   = (const float*)d_in[9];
    const float* b_ih   = (const float*)d_in[10];
    const float* b_hh   = (const float*)d_in[11];
    const float* fc_W   = (const float*)d_in[12];
    const float* fc_b   = (const float*)d_in[13];

    void *pAWx, *pAWh, *pAb, *pWih, *pBih, *pBhh, *pCWx, *pCb, *pFcW, *pFcb;
    cudaGetSymbolAddress(&pAWx, cAWx);
    cudaGetSymbolAddress(&pAWh, cAWh);
    cudaGetSymbolAddress(&pAb,  cAb);
    cudaGetSymbolAddress(&pWih, cWih);
    cudaGetSymbolAddress(&pBih, cBih);
    cudaGetSymbolAddress(&pBhh, cBhh);
    cudaGetSymbolAddress(&pCWx, cCWx);
    cudaGetSymbolAddress(&pCb,  cCb);
    cudaGetSymbolAddress(&pFcW, cFcW);
    cudaGetSymbolAddress(&pFcb, cFcb);

    // attn_W [48][36] -> x part [48][4] and h part [48][32]
    cudaMemcpy2DAsync(pAWx, 16, attn_W, 144, 16, 48, cudaMemcpyDeviceToDevice, 0);
    cudaMemcpy2DAsync(pAWh, 128, attn_W + 16, 144, 128, 48, cudaMemcpyDeviceToDevice, 0);
    // comb_W [4][132] -> x tail [4][4]
    cudaMemcpy2DAsync(pCWx, 16, (const char*)comb_W + 512, 528, 16, 4, cudaMemcpyDeviceToDevice, 0);
    cudaMemcpyAsync(pAb,  attn_b, 48 * 4,  cudaMemcpyDeviceToDevice, 0);
    cudaMemcpyAsync(pWih, w_ih, 96 * 4 * 4, cudaMemcpyDeviceToDevice, 0);
    cudaMemcpyAsync(pBih, b_ih, 96 * 4, cudaMemcpyDeviceToDevice, 0);
    cudaMemcpyAsync(pBhh, b_hh, 96 * 4, cudaMemcpyDeviceToDevice, 0);
    cudaMemcpyAsync(pCb,  comb_b, 4 * 4, cudaMemcpyDeviceToDevice, 0);
    cudaMemcpyAsync(pFcW, fc_W, 32 * 4, cudaMemcpyDeviceToDevice, 0);
    cudaMemcpyAsync(pFcb, fc_b, 4, cudaMemcpyDeviceToDevice, 0);

    fused_decoder<<<B / 32, 128>>>(y, enc, hidden, comb_W, w_hh, (float*)d_out);
}